// round 5
// baseline (speedup 1.0000x reference)
#include <cuda_runtime.h>
#include <cuda_bf16.h>
#include <cstdint>
#include <math.h>

#define N 2048
#define K 4096
#define ROUNDS 11
#define STAGES 3
#define BK 64
#define CHUNKS (K / BK)
#define STAGE_BYTES 32768
#define PBLKS 148
#define PTHR 256

typedef unsigned long long ull;

// ---------------- device scratch ----------------
__device__ float         g_D[(size_t)N * N];     // 16 MB
__device__ __nv_bfloat16 g_Xb[(size_t)N * K];    // 16 MB
__device__ float         g_sq[N];
__device__ int           g_parent[N];
__device__ int           g_root[N];
__device__ ull           g_minER[ROUNDS][N];
__device__ float         g_edgeW[N];
__device__ int           g_cnt;
__device__ unsigned      g_barCount;              // always 0 outside an active barrier
__device__ volatile unsigned g_barSense;          // never reset; CTAs sample it at entry

// ---------------- helpers ----------------
__device__ __forceinline__ uint32_t s2u(const void* p) {
    return (uint32_t)__cvta_generic_to_shared(p);
}
__device__ __forceinline__ void cp16(uint32_t dst, const void* src) {
    asm volatile("cp.async.cg.shared.global [%0], [%1], 16;" :: "r"(dst), "l"(src) : "memory");
}
__device__ __forceinline__ uint32_t swz(uint32_t off) {
    return off ^ ((off >> 3) & 0x70);
}
__device__ __forceinline__ void ldmx4(uint32_t* r, uint32_t addr) {
    asm volatile("ldmatrix.sync.aligned.m8n8.x4.shared.b16 {%0,%1,%2,%3}, [%4];"
                 : "=r"(r[0]), "=r"(r[1]), "=r"(r[2]), "=r"(r[3]) : "r"(addr));
}
__device__ __forceinline__ void mma16816(float* d, const uint32_t* a, uint32_t b0, uint32_t b1) {
    asm volatile(
        "mma.sync.aligned.m16n8k16.row.col.f32.bf16.bf16.f32 "
        "{%0,%1,%2,%3}, {%4,%5,%6,%7}, {%8,%9}, {%0,%1,%2,%3};"
        : "+f"(d[0]), "+f"(d[1]), "+f"(d[2]), "+f"(d[3])
        : "r"(a[0]), "r"(a[1]), "r"(a[2]), "r"(a[3]), "r"(b0), "r"(b1));
}

// sense-reversing software grid barrier; NO runtime resets anywhere.
__device__ __forceinline__ void gbar(unsigned* ls) {
    __threadfence();
    __syncthreads();
    if (threadIdx.x == 0) {
        unsigned s = *ls ^ 1u;
        *ls = s;
        unsigned old = atomicAdd(&g_barCount, 1u);
        if (old == PBLKS - 1) {
            g_barCount = 0;          // safe: all arrivals in, no concurrent RMW
            __threadfence();
            g_barSense = s;
        } else {
            while (g_barSense != s) __nanosleep(64);
        }
        __threadfence();
    }
    __syncthreads();
}

// ---------------- 1) fused fp32->bf16 convert + row squared norms ----------------
__global__ void prep_kernel(const float* __restrict__ x) {
    int row = blockIdx.x;
    int tid = threadIdx.x;
    const float4* xr = (const float4*)(x + (size_t)row * K);
    __nv_bfloat16* xb = g_Xb + (size_t)row * K;
    float s = 0.f;
    #pragma unroll 4
    for (int i = tid; i < K / 4; i += 256) {
        float4 v = xr[i];
        s += v.x * v.x + v.y * v.y + v.z * v.z + v.w * v.w;
        *(__nv_bfloat162*)(xb + i * 4)     = __floats2bfloat162_rn(v.x, v.y);
        *(__nv_bfloat162*)(xb + i * 4 + 2) = __floats2bfloat162_rn(v.z, v.w);
    }
    for (int o = 16; o > 0; o >>= 1) s += __shfl_down_sync(0xffffffffu, s, o);
    __shared__ float ws[8];
    if ((tid & 31) == 0) ws[tid >> 5] = s;
    __syncthreads();
    if (tid == 0) {
        float t = 0.f;
        #pragma unroll
        for (int w = 0; w < 8; w++) t += ws[w];
        g_sq[row] = t;
    }
}

// ---------------- 2) bf16 HMMA GEMM + distance epilogue ----------------
__global__ void __launch_bounds__(256, 1) gemm_dist_kernel() {
    extern __shared__ char smem[];
    const int bx = blockIdx.x, by = blockIdx.y;
    if (bx > by) return;

    const int tid  = threadIdx.x;
    const int wid  = tid >> 5;
    const int lane = tid & 31;
    const int wr   = wid >> 1;
    const int wc   = wid & 1;

    uint32_t sb = s2u(smem);
    uint32_t stage_base = (sb + 1023) & ~1023u;

    __shared__ float sqi_s[128], sqj_s[128];

    const __nv_bfloat16* gA = g_Xb + (size_t)(by * 128) * K;
    const __nv_bfloat16* gB = g_Xb + (size_t)(bx * 128) * K;

    auto load_stage = [&](int s, int chunk) {
        uint32_t bA = stage_base + s * STAGE_BYTES;
        uint32_t bB = bA + 16384;
        size_t kb = (size_t)chunk * BK * 2;
        #pragma unroll
        for (int it = 0; it < 4; it++) {
            int q = tid + it * 256;
            int r = q >> 3, c = q & 7;
            uint32_t sw = swz((uint32_t)(r * 128 + c * 16));
            cp16(bA + sw, (const char*)(gA + (size_t)r * K) + kb + c * 16);
            cp16(bB + sw, (const char*)(gB + (size_t)r * K) + kb + c * 16);
        }
    };

    float acc[2][8][4];
    #pragma unroll
    for (int i = 0; i < 2; i++)
        #pragma unroll
        for (int j = 0; j < 8; j++)
            #pragma unroll
            for (int c = 0; c < 4; c++) acc[i][j][c] = 0.f;

    load_stage(0, 0);
    asm volatile("cp.async.commit_group;" ::: "memory");
    load_stage(1, 1);
    asm volatile("cp.async.commit_group;" ::: "memory");

    const int rowA0 = wr * 32 + (lane & 15);
    const int rowB0 = wc * 64 + (lane & 15);
    const int hb    = (lane >> 4) * 16;

    for (int c = 0; c < CHUNKS; c++) {
        int s = c % STAGES;
        asm volatile("cp.async.wait_group 1;" ::: "memory");
        __syncthreads();

        if (c + 2 < CHUNKS) load_stage((c + 2) % STAGES, c + 2);
        asm volatile("cp.async.commit_group;" ::: "memory");

        uint32_t bA = stage_base + s * STAGE_BYTES;
        uint32_t bB = bA + 16384;

        #pragma unroll
        for (int kk = 0; kk < 4; kk++) {
            uint32_t a[2][4];
            #pragma unroll
            for (int mi = 0; mi < 2; mi++)
                ldmx4(a[mi], bA + swz((uint32_t)((rowA0 + mi * 16) * 128 + kk * 32 + hb)));
            uint32_t b[4][4];
            #pragma unroll
            for (int nb = 0; nb < 4; nb++)
                ldmx4(b[nb], bB + swz((uint32_t)((rowB0 + nb * 16) * 128 + kk * 32 + hb)));
            #pragma unroll
            for (int mi = 0; mi < 2; mi++)
                #pragma unroll
                for (int nb = 0; nb < 4; nb++) {
                    mma16816(acc[mi][nb * 2],     a[mi], b[nb][0], b[nb][2]);
                    mma16816(acc[mi][nb * 2 + 1], a[mi], b[nb][1], b[nb][3]);
                }
        }
    }

    if (tid < 128) {
        sqi_s[tid] = g_sq[by * 128 + tid];
        sqj_s[tid] = g_sq[bx * 128 + tid];
    }
    __syncthreads();

    float* tbuf = (float*)(smem + (stage_base - sb));   // 128 x 129 fp32

    #pragma unroll
    for (int mi = 0; mi < 2; mi++)
        #pragma unroll
        for (int ni = 0; ni < 8; ni++)
            #pragma unroll
            for (int cc = 0; cc < 4; cc++) {
                int row = wr * 32 + mi * 16 + (lane >> 2) + ((cc >> 1) * 8);
                int col = wc * 64 + ni * 8 + (lane & 3) * 2 + (cc & 1);
                float d2 = sqi_s[row] + sqj_s[col] - 2.f * acc[mi][ni][cc];
                tbuf[row * 129 + col] = sqrtf(fmaxf(d2, 0.f));
            }
    __syncthreads();

    int col = tid & 127, r0 = tid >> 7;
    for (int rr = r0; rr < 128; rr += 2)
        g_D[(size_t)(by * 128 + rr) * N + bx * 128 + col] = tbuf[rr * 129 + col];
    if (bx != by)
        for (int rr = r0; rr < 128; rr += 2)
            g_D[(size_t)(bx * 128 + rr) * N + by * 128 + col] = tbuf[col * 129 + rr];
}

// ---------------- 3) persistent Boruvka MST + sort (single launch) ----------------
__global__ void __launch_bounds__(PTHR, 1) mst_kernel(float* __restrict__ out) {
    __shared__ int  sroot[N];            // 8KB; aliased as sort buffer at the end
    __shared__ ull  sred[8];
    const int bid  = blockIdx.x;
    const int tid  = threadIdx.x;
    const int gtid = bid * PTHR + tid;
    const int lane = tid & 31;
    const int wrp  = tid >> 5;

    // Seed local sense from current global sense (no writer is active at entry;
    // all CTAs read the same stable value). NO resets of barrier vars anywhere.
    unsigned ls = g_barSense;

    if (gtid == 0) g_cnt = 0;            // ordered: written before CTA0's first gbar arrival
    for (int i = gtid; i < N; i += PBLKS * PTHR) g_parent[i] = i;
    for (int i = gtid; i < ROUNDS * N; i += PBLKS * PTHR) ((ull*)g_minER)[i] = ~0ull;
    gbar(&ls);

    for (int r = 0; r < ROUNDS; r++) {
        // roots of all vertices into smem (parents frozen since last barrier)
        for (int j = tid; j < N; j += PTHR) {
            int p = g_parent[j];
            int pp = g_parent[p];
            while (pp != p) { p = pp; pp = g_parent[p]; }
            sroot[j] = p;
            if (bid == 0) g_root[j] = p;   // frozen snapshot for merge phase
        }
        __syncthreads();

        // scan assigned vertices: min outgoing edge -> atomicMin per component
        for (int v = bid; v < N; v += PBLKS) {
            int cv = sroot[v];
            const float* __restrict__ row = g_D + (size_t)v * N;
            ull best = ~0ull;
            for (int j = tid; j < N; j += PTHR) {
                if (sroot[j] != cv) {
                    float w = row[j];
                    unsigned p = (v < j) ? (unsigned)(v * N + j) : (unsigned)(j * N + v);
                    ull key = ((ull)__float_as_uint(w) << 32) | p;
                    best = min(best, key);
                }
            }
            #pragma unroll
            for (int o = 16; o > 0; o >>= 1)
                best = min(best, __shfl_down_sync(0xffffffffu, best, o));
            if (lane == 0) sred[wrp] = best;
            __syncthreads();
            if (tid == 0) {
                ull m = sred[0];
                #pragma unroll
                for (int w = 1; w < 8; w++) m = min(m, sred[w]);
                if (m != ~0ull) atomicMin(&g_minER[r][cv], m);
            }
            __syncthreads();
        }
        gbar(&ls);

        // merge: one thread per component root
        if (gtid < N) {
            int c = gtid;
            if (g_parent[c] == c) {
                ull key = g_minER[r][c];
                if (key != ~0ull) {
                    unsigned p = (unsigned)key;
                    int a = p / N, b = p % N;
                    int ra = g_root[a], rb = g_root[b];
                    int rd = (ra == c) ? rb : ra;
                    bool skip = false;
                    ull key2 = g_minER[r][rd];
                    if (key2 != ~0ull) {
                        unsigned p2 = (unsigned)key2;
                        int a2 = p2 / N, b2 = p2 % N;
                        int ra2 = g_root[a2], rb2 = g_root[b2];
                        int tgt = (ra2 == rd) ? rb2 : ra2;
                        if (tgt == c && c > rd) skip = true;
                    }
                    if (!skip) {
                        g_parent[c] = rd;
                        float w = __uint_as_float((unsigned)(key >> 32));
                        g_edgeW[atomicAdd(&g_cnt, 1)] = w;
                    }
                }
            }
        }
        gbar(&ls);

        int cnt = *(volatile int*)&g_cnt;   // uniform across grid post-barrier
        if (cnt == N - 1) break;            // uniform branch: all CTAs agree
    }

    // CTA 0: bitonic sort the N-1 weights ascending, write output
    if (bid != 0) return;
    float* sw = (float*)sroot;
    for (int i = tid; i < N; i += PTHR)
        sw[i] = (i < N - 1) ? g_edgeW[i] : 3.4028235e38f;
    __syncthreads();
    for (int k = 2; k <= N; k <<= 1) {
        for (int j = k >> 1; j > 0; j >>= 1) {
            for (int i = tid; i < N; i += PTHR) {
                int l = i ^ j;
                if (l > i) {
                    bool up = ((i & k) == 0);
                    float a = sw[i], b = sw[l];
                    if ((a > b) == up) { sw[i] = b; sw[l] = a; }
                }
            }
            __syncthreads();
        }
    }
    for (int i = tid; i < N - 1; i += PTHR) out[i] = sw[i];
}

// ---------------- launch ----------------
extern "C" void kernel_launch(void* const* d_in, const int* in_sizes, int n_in,
                              void* d_out, int out_size) {
    const float* x = (const float*)d_in[0];
    float* out = (float*)d_out;

    prep_kernel<<<N, 256>>>(x);

    static const int SMEM_SZ = STAGES * STAGE_BYTES + 1024;
    cudaFuncSetAttribute(gemm_dist_kernel,
                         cudaFuncAttributeMaxDynamicSharedMemorySize, SMEM_SZ);
    gemm_dist_kernel<<<dim3(16, 16), 256, SMEM_SZ>>>();

    mst_kernel<<<PBLKS, PTHR>>>(out);
}

// round 6
// speedup vs baseline: 1.3621x; 1.3621x over previous
#include <cuda_runtime.h>
#include <cuda_bf16.h>
#include <cstdint>
#include <math.h>

#define N 2048
#define K 4096
#define ROUNDS 11
#define STAGES 3
#define BK 64
#define CHUNKS (K / BK)
#define STAGE_BYTES 32768
#define MBLKS 32
#define MTHR 512

typedef unsigned long long ull;

// ---------------- device scratch ----------------
__device__ float         g_D[(size_t)N * N];     // 16 MB
__device__ __nv_bfloat16 g_Xb[(size_t)N * K];    // 16 MB
__device__ float         g_sq[N];
__device__ int           g_parent[N];
__device__ int           g_root[N];
__device__ ull           g_minER[ROUNDS][N];
__device__ float         g_edgeW[N];
__device__ int           g_cnt;
__device__ unsigned      g_barCount;              // always 0 outside an active barrier
__device__ volatile unsigned g_barSense;          // never reset; sampled at kernel entry

// ---------------- helpers ----------------
__device__ __forceinline__ uint32_t s2u(const void* p) {
    return (uint32_t)__cvta_generic_to_shared(p);
}
__device__ __forceinline__ void cp16(uint32_t dst, const void* src) {
    asm volatile("cp.async.cg.shared.global [%0], [%1], 16;" :: "r"(dst), "l"(src) : "memory");
}
__device__ __forceinline__ uint32_t swz(uint32_t off) {
    return off ^ ((off >> 3) & 0x70);
}
__device__ __forceinline__ void ldmx4(uint32_t* r, uint32_t addr) {
    asm volatile("ldmatrix.sync.aligned.m8n8.x4.shared.b16 {%0,%1,%2,%3}, [%4];"
                 : "=r"(r[0]), "=r"(r[1]), "=r"(r[2]), "=r"(r[3]) : "r"(addr));
}
__device__ __forceinline__ void mma16816(float* d, const uint32_t* a, uint32_t b0, uint32_t b1) {
    asm volatile(
        "mma.sync.aligned.m16n8k16.row.col.f32.bf16.bf16.f32 "
        "{%0,%1,%2,%3}, {%4,%5,%6,%7}, {%8,%9}, {%0,%1,%2,%3};"
        : "+f"(d[0]), "+f"(d[1]), "+f"(d[2]), "+f"(d[3])
        : "r"(a[0]), "r"(a[1]), "r"(a[2]), "r"(a[3]), "r"(b0), "r"(b1));
}

// sense-reversing software grid barrier; no runtime resets anywhere.
__device__ __forceinline__ void gbar(unsigned* ls) {
    __threadfence();
    __syncthreads();
    if (threadIdx.x == 0) {
        unsigned s = *ls ^ 1u;
        *ls = s;
        unsigned old = atomicAdd(&g_barCount, 1u);
        if (old == MBLKS - 1) {
            g_barCount = 0;          // all arrivals in; no concurrent RMW
            __threadfence();
            g_barSense = s;
        } else {
            while (g_barSense != s) __nanosleep(32);
        }
        __threadfence();
    }
    __syncthreads();
}

// ---------------- 1) fused fp32->bf16 convert + row squared norms ----------------
__global__ void prep_kernel(const float* __restrict__ x) {
    int row = blockIdx.x;
    int tid = threadIdx.x;
    const float4* xr = (const float4*)(x + (size_t)row * K);
    __nv_bfloat16* xb = g_Xb + (size_t)row * K;
    float s = 0.f;
    #pragma unroll 4
    for (int i = tid; i < K / 4; i += 256) {
        float4 v = xr[i];
        s += v.x * v.x + v.y * v.y + v.z * v.z + v.w * v.w;
        *(__nv_bfloat162*)(xb + i * 4)     = __floats2bfloat162_rn(v.x, v.y);
        *(__nv_bfloat162*)(xb + i * 4 + 2) = __floats2bfloat162_rn(v.z, v.w);
    }
    for (int o = 16; o > 0; o >>= 1) s += __shfl_down_sync(0xffffffffu, s, o);
    __shared__ float ws[8];
    if ((tid & 31) == 0) ws[tid >> 5] = s;
    __syncthreads();
    if (tid == 0) {
        float t = 0.f;
        #pragma unroll
        for (int w = 0; w < 8; w++) t += ws[w];
        g_sq[row] = t;
    }
}

// ---------------- 2) bf16 HMMA GEMM + distance epilogue ----------------
__global__ void __launch_bounds__(256, 1) gemm_dist_kernel() {
    extern __shared__ char smem[];
    const int bx = blockIdx.x, by = blockIdx.y;
    if (bx > by) return;

    const int tid  = threadIdx.x;
    const int wid  = tid >> 5;
    const int lane = tid & 31;
    const int wr   = wid >> 1;
    const int wc   = wid & 1;

    uint32_t sb = s2u(smem);
    uint32_t stage_base = (sb + 1023) & ~1023u;

    __shared__ float sqi_s[128], sqj_s[128];

    const __nv_bfloat16* gA = g_Xb + (size_t)(by * 128) * K;
    const __nv_bfloat16* gB = g_Xb + (size_t)(bx * 128) * K;

    auto load_stage = [&](int s, int chunk) {
        uint32_t bA = stage_base + s * STAGE_BYTES;
        uint32_t bB = bA + 16384;
        size_t kb = (size_t)chunk * BK * 2;
        #pragma unroll
        for (int it = 0; it < 4; it++) {
            int q = tid + it * 256;
            int r = q >> 3, c = q & 7;
            uint32_t sw = swz((uint32_t)(r * 128 + c * 16));
            cp16(bA + sw, (const char*)(gA + (size_t)r * K) + kb + c * 16);
            cp16(bB + sw, (const char*)(gB + (size_t)r * K) + kb + c * 16);
        }
    };

    float acc[2][8][4];
    #pragma unroll
    for (int i = 0; i < 2; i++)
        #pragma unroll
        for (int j = 0; j < 8; j++)
            #pragma unroll
            for (int c = 0; c < 4; c++) acc[i][j][c] = 0.f;

    load_stage(0, 0);
    asm volatile("cp.async.commit_group;" ::: "memory");
    load_stage(1, 1);
    asm volatile("cp.async.commit_group;" ::: "memory");

    const int rowA0 = wr * 32 + (lane & 15);
    const int rowB0 = wc * 64 + (lane & 15);
    const int hb    = (lane >> 4) * 16;

    for (int c = 0; c < CHUNKS; c++) {
        int s = c % STAGES;
        asm volatile("cp.async.wait_group 1;" ::: "memory");
        __syncthreads();

        if (c + 2 < CHUNKS) load_stage((c + 2) % STAGES, c + 2);
        asm volatile("cp.async.commit_group;" ::: "memory");

        uint32_t bA = stage_base + s * STAGE_BYTES;
        uint32_t bB = bA + 16384;

        // register double-buffered kk pipeline
        uint32_t abuf[2][2][4], bbuf[2][4][4];
        #pragma unroll
        for (int mi = 0; mi < 2; mi++)
            ldmx4(abuf[0][mi], bA + swz((uint32_t)((rowA0 + mi * 16) * 128 + hb)));
        #pragma unroll
        for (int nb = 0; nb < 4; nb++)
            ldmx4(bbuf[0][nb], bB + swz((uint32_t)((rowB0 + nb * 16) * 128 + hb)));

        #pragma unroll
        for (int kk = 0; kk < 4; kk++) {
            int cur = kk & 1, nxt = cur ^ 1;
            if (kk < 3) {
                #pragma unroll
                for (int mi = 0; mi < 2; mi++)
                    ldmx4(abuf[nxt][mi],
                          bA + swz((uint32_t)((rowA0 + mi * 16) * 128 + (kk + 1) * 32 + hb)));
                #pragma unroll
                for (int nb = 0; nb < 4; nb++)
                    ldmx4(bbuf[nxt][nb],
                          bB + swz((uint32_t)((rowB0 + nb * 16) * 128 + (kk + 1) * 32 + hb)));
            }
            #pragma unroll
            for (int mi = 0; mi < 2; mi++)
                #pragma unroll
                for (int nb = 0; nb < 4; nb++) {
                    mma16816(acc[mi][nb * 2],     abuf[cur][mi], bbuf[cur][nb][0], bbuf[cur][nb][2]);
                    mma16816(acc[mi][nb * 2 + 1], abuf[cur][mi], bbuf[cur][nb][1], bbuf[cur][nb][3]);
                }
        }
    }

    if (tid < 128) {
        sqi_s[tid] = g_sq[by * 128 + tid];
        sqj_s[tid] = g_sq[bx * 128 + tid];
    }
    __syncthreads();

    float* tbuf = (float*)(smem + (stage_base - sb));   // 128 x 129 fp32

    #pragma unroll
    for (int mi = 0; mi < 2; mi++)
        #pragma unroll
        for (int ni = 0; ni < 8; ni++)
            #pragma unroll
            for (int cc = 0; cc < 4; cc++) {
                int row = wr * 32 + mi * 16 + (lane >> 2) + ((cc >> 1) * 8);
                int col = wc * 64 + ni * 8 + (lane & 3) * 2 + (cc & 1);
                float d2 = sqi_s[row] + sqj_s[col] - 2.f * acc[mi][ni][cc];
                tbuf[row * 129 + col] = sqrtf(fmaxf(d2, 0.f));
            }
    __syncthreads();

    int col = tid & 127, r0 = tid >> 7;
    for (int rr = r0; rr < 128; rr += 2)
        g_D[(size_t)(by * 128 + rr) * N + bx * 128 + col] = tbuf[rr * 129 + col];
    if (bx != by)
        for (int rr = r0; rr < 128; rr += 2)
            g_D[(size_t)(bx * 128 + rr) * N + by * 128 + col] = tbuf[col * 129 + rr];
}

// ---------------- 3) persistent Boruvka MST + sort (single launch) ----------------
__global__ void __launch_bounds__(MTHR, 1) mst_kernel(float* __restrict__ out) {
    __shared__ int sroot[N];             // 8KB; aliased as sort buffer at the end
    const int bid  = blockIdx.x;
    const int tid  = threadIdx.x;
    const int gtid = bid * MTHR + tid;
    const int lane = tid & 31;
    const int wrp  = tid >> 5;
    const int WPC  = MTHR / 32;          // warps per CTA
    const int NW   = MBLKS * WPC;        // total warps

    unsigned ls = g_barSense;            // stable at entry; no resets anywhere

    if (gtid == 0) g_cnt = 0;
    for (int i = gtid; i < N; i += MBLKS * MTHR) g_parent[i] = i;
    for (int i = gtid; i < ROUNDS * N; i += MBLKS * MTHR) ((ull*)g_minER)[i] = ~0ull;
    gbar(&ls);

    for (int r = 0; r < ROUNDS; r++) {
        // roots of all vertices into smem (parents frozen since last barrier)
        for (int j = tid; j < N; j += MTHR) {
            int p = g_parent[j];
            int pp = g_parent[p];
            while (pp != p) { p = pp; pp = g_parent[p]; }
            sroot[j] = p;
            if (bid == 0) g_root[j] = p;   // frozen snapshot for merge phase
        }
        __syncthreads();

        // warp-per-vertex scan: min outgoing edge -> one atomicMin per (warp,vertex)
        for (int v = bid * WPC + wrp; v < N; v += NW) {
            int cv = sroot[v];
            const float4* __restrict__ row4 = (const float4*)(g_D + (size_t)v * N);
            ull best = ~0ull;
            #pragma unroll 4
            for (int q = lane; q < N / 4; q += 32) {
                float4 w4 = row4[q];
                int j = q * 4;
                if (sroot[j]     != cv) best = min(best, (((ull)__float_as_uint(w4.x)) << 32) | (unsigned)((v << 11) | j));
                if (sroot[j + 1] != cv) best = min(best, (((ull)__float_as_uint(w4.y)) << 32) | (unsigned)((v << 11) | (j + 1)));
                if (sroot[j + 2] != cv) best = min(best, (((ull)__float_as_uint(w4.z)) << 32) | (unsigned)((v << 11) | (j + 2)));
                if (sroot[j + 3] != cv) best = min(best, (((ull)__float_as_uint(w4.w)) << 32) | (unsigned)((v << 11) | (j + 3)));
            }
            #pragma unroll
            for (int o = 16; o > 0; o >>= 1)
                best = min(best, __shfl_down_sync(0xffffffffu, best, o));
            if (lane == 0 && best != ~0ull) atomicMin(&g_minER[r][cv], best);
        }
        gbar(&ls);

        // merge: one thread per component root
        if (gtid < N) {
            int c = gtid;
            if (g_parent[c] == c) {
                ull key = g_minER[r][c];
                if (key != ~0ull) {
                    unsigned p = (unsigned)key;
                    int a = (p >> 11) & 2047, b = p & 2047;
                    int ra = g_root[a], rb = g_root[b];
                    int rd = (ra == c) ? rb : ra;
                    bool skip = false;
                    ull key2 = g_minER[r][rd];
                    if (key2 != ~0ull) {
                        unsigned p2 = (unsigned)key2;
                        int a2 = (p2 >> 11) & 2047, b2 = p2 & 2047;
                        int ra2 = g_root[a2], rb2 = g_root[b2];
                        int tgt = (ra2 == rd) ? rb2 : ra2;
                        if (tgt == c && c > rd) skip = true;
                    }
                    if (!skip) {
                        g_parent[c] = rd;
                        float w = __uint_as_float((unsigned)(key >> 32));
                        g_edgeW[atomicAdd(&g_cnt, 1)] = w;
                    }
                }
            }
        }
        gbar(&ls);

        int cnt = *(volatile int*)&g_cnt;   // uniform across grid post-barrier
        if (cnt == N - 1) break;
    }

    // CTA 0: bitonic sort the N-1 weights ascending, write output
    if (bid != 0) return;
    float* sw = (float*)sroot;
    for (int i = tid; i < N; i += MTHR)
        sw[i] = (i < N - 1) ? g_edgeW[i] : 3.4028235e38f;
    __syncthreads();
    for (int k = 2; k <= N; k <<= 1) {
        for (int j = k >> 1; j > 0; j >>= 1) {
            for (int i = tid; i < N; i += MTHR) {
                int l = i ^ j;
                if (l > i) {
                    bool up = ((i & k) == 0);
                    float a = sw[i], b = sw[l];
                    if ((a > b) == up) { sw[i] = b; sw[l] = a; }
                }
            }
            __syncthreads();
        }
    }
    for (int i = tid; i < N - 1; i += MTHR) out[i] = sw[i];
}

// ---------------- launch ----------------
extern "C" void kernel_launch(void* const* d_in, const int* in_sizes, int n_in,
                              void* d_out, int out_size) {
    const float* x = (const float*)d_in[0];
    float* out = (float*)d_out;

    prep_kernel<<<N, 256>>>(x);

    static const int SMEM_SZ = STAGES * STAGE_BYTES + 1024;
    cudaFuncSetAttribute(gemm_dist_kernel,
                         cudaFuncAttributeMaxDynamicSharedMemorySize, SMEM_SZ);
    gemm_dist_kernel<<<dim3(16, 16), 256, SMEM_SZ>>>();

    mst_kernel<<<MBLKS, MTHR>>>(out);
}

// round 7
// speedup vs baseline: 1.4166x; 1.0401x over previous
#include <cuda_runtime.h>
#include <cuda_bf16.h>
#include <cuda_fp16.h>
#include <cstdint>
#include <math.h>

#define N 2048
#define K 4096
#define ROUNDS 11
#define STAGES 3
#define BK 64
#define CHUNKS (K / BK)
#define STAGE_BYTES 32768
#define MBLKS 32
#define MTHR 512

typedef unsigned long long ull;

// ---------------- device scratch ----------------
__device__ __half        g_Dh[(size_t)N * N];    // 8 MB fp16 distance matrix
__device__ __nv_bfloat16 g_Xb[(size_t)N * K];    // 16 MB
__device__ float         g_sq[N];
__device__ int           g_parent[N];
__device__ int           g_root[N];
__device__ ull           g_minER[ROUNDS][N];
__device__ unsigned      g_edgeP[N];             // packed (v<<11)|j pairs
__device__ int           g_cnt;
__device__ unsigned      g_barCount;
__device__ volatile unsigned g_barSense;

// ---------------- helpers ----------------
__device__ __forceinline__ uint32_t s2u(const void* p) {
    return (uint32_t)__cvta_generic_to_shared(p);
}
__device__ __forceinline__ void cp16(uint32_t dst, const void* src) {
    asm volatile("cp.async.cg.shared.global [%0], [%1], 16;" :: "r"(dst), "l"(src) : "memory");
}
__device__ __forceinline__ uint32_t swz(uint32_t off) {
    return off ^ ((off >> 3) & 0x70);
}
__device__ __forceinline__ void ldmx4(uint32_t* r, uint32_t addr) {
    asm volatile("ldmatrix.sync.aligned.m8n8.x4.shared.b16 {%0,%1,%2,%3}, [%4];"
                 : "=r"(r[0]), "=r"(r[1]), "=r"(r[2]), "=r"(r[3]) : "r"(addr));
}
__device__ __forceinline__ void mma16816(float* d, const uint32_t* a, uint32_t b0, uint32_t b1) {
    asm volatile(
        "mma.sync.aligned.m16n8k16.row.col.f32.bf16.bf16.f32 "
        "{%0,%1,%2,%3}, {%4,%5,%6,%7}, {%8,%9}, {%0,%1,%2,%3};"
        : "+f"(d[0]), "+f"(d[1]), "+f"(d[2]), "+f"(d[3])
        : "r"(a[0]), "r"(a[1]), "r"(a[2]), "r"(a[3]), "r"(b0), "r"(b1));
}

__device__ __forceinline__ void gbar(unsigned* ls) {
    __threadfence();
    __syncthreads();
    if (threadIdx.x == 0) {
        unsigned s = *ls ^ 1u;
        *ls = s;
        unsigned old = atomicAdd(&g_barCount, 1u);
        if (old == MBLKS - 1) {
            g_barCount = 0;
            __threadfence();
            g_barSense = s;
        } else {
            while (g_barSense != s) __nanosleep(32);
        }
        __threadfence();
    }
    __syncthreads();
}

// ---------------- 1) fused convert + row squared norms ----------------
__global__ void prep_kernel(const float* __restrict__ x) {
    int row = blockIdx.x;
    int tid = threadIdx.x;
    const float4* xr = (const float4*)(x + (size_t)row * K);
    __nv_bfloat16* xb = g_Xb + (size_t)row * K;
    float s = 0.f;
    #pragma unroll 4
    for (int i = tid; i < K / 4; i += 256) {
        float4 v = xr[i];
        s += v.x * v.x + v.y * v.y + v.z * v.z + v.w * v.w;
        *(__nv_bfloat162*)(xb + i * 4)     = __floats2bfloat162_rn(v.x, v.y);
        *(__nv_bfloat162*)(xb + i * 4 + 2) = __floats2bfloat162_rn(v.z, v.w);
    }
    for (int o = 16; o > 0; o >>= 1) s += __shfl_down_sync(0xffffffffu, s, o);
    __shared__ float ws[8];
    if ((tid & 31) == 0) ws[tid >> 5] = s;
    __syncthreads();
    if (tid == 0) {
        float t = 0.f;
        #pragma unroll
        for (int w = 0; w < 8; w++) t += ws[w];
        g_sq[row] = t;
    }
}

// ---------------- 2) bf16 HMMA GEMM + fp16 distance epilogue ----------------
__global__ void __launch_bounds__(256, 1) gemm_dist_kernel() {
    extern __shared__ char smem[];
    const int bx = blockIdx.x, by = blockIdx.y;
    if (bx > by) return;

    const int tid  = threadIdx.x;
    const int wid  = tid >> 5;
    const int lane = tid & 31;
    const int wr   = wid >> 1;
    const int wc   = wid & 1;

    uint32_t sb = s2u(smem);
    uint32_t stage_base = (sb + 1023) & ~1023u;

    __shared__ float sqi_s[128], sqj_s[128];

    const __nv_bfloat16* gA = g_Xb + (size_t)(by * 128) * K;
    const __nv_bfloat16* gB = g_Xb + (size_t)(bx * 128) * K;

    auto load_stage = [&](int s, int chunk) {
        uint32_t bA = stage_base + s * STAGE_BYTES;
        uint32_t bB = bA + 16384;
        size_t kb = (size_t)chunk * BK * 2;
        #pragma unroll
        for (int it = 0; it < 4; it++) {
            int q = tid + it * 256;
            int r = q >> 3, c = q & 7;
            uint32_t sw = swz((uint32_t)(r * 128 + c * 16));
            cp16(bA + sw, (const char*)(gA + (size_t)r * K) + kb + c * 16);
            cp16(bB + sw, (const char*)(gB + (size_t)r * K) + kb + c * 16);
        }
    };

    float acc[2][8][4];
    #pragma unroll
    for (int i = 0; i < 2; i++)
        #pragma unroll
        for (int j = 0; j < 8; j++)
            #pragma unroll
            for (int c = 0; c < 4; c++) acc[i][j][c] = 0.f;

    load_stage(0, 0);
    asm volatile("cp.async.commit_group;" ::: "memory");
    load_stage(1, 1);
    asm volatile("cp.async.commit_group;" ::: "memory");

    const int rowA0 = wr * 32 + (lane & 15);
    const int rowB0 = wc * 64 + (lane & 15);
    const int hb    = (lane >> 4) * 16;

    for (int c = 0; c < CHUNKS; c++) {
        int s = c % STAGES;
        asm volatile("cp.async.wait_group 1;" ::: "memory");
        __syncthreads();

        if (c + 2 < CHUNKS) load_stage((c + 2) % STAGES, c + 2);
        asm volatile("cp.async.commit_group;" ::: "memory");

        uint32_t bA = stage_base + s * STAGE_BYTES;
        uint32_t bB = bA + 16384;

        uint32_t abuf[2][2][4], bbuf[2][4][4];
        #pragma unroll
        for (int mi = 0; mi < 2; mi++)
            ldmx4(abuf[0][mi], bA + swz((uint32_t)((rowA0 + mi * 16) * 128 + hb)));
        #pragma unroll
        for (int nb = 0; nb < 4; nb++)
            ldmx4(bbuf[0][nb], bB + swz((uint32_t)((rowB0 + nb * 16) * 128 + hb)));

        #pragma unroll
        for (int kk = 0; kk < 4; kk++) {
            int cur = kk & 1, nxt = cur ^ 1;
            if (kk < 3) {
                #pragma unroll
                for (int mi = 0; mi < 2; mi++)
                    ldmx4(abuf[nxt][mi],
                          bA + swz((uint32_t)((rowA0 + mi * 16) * 128 + (kk + 1) * 32 + hb)));
                #pragma unroll
                for (int nb = 0; nb < 4; nb++)
                    ldmx4(bbuf[nxt][nb],
                          bB + swz((uint32_t)((rowB0 + nb * 16) * 128 + (kk + 1) * 32 + hb)));
            }
            #pragma unroll
            for (int mi = 0; mi < 2; mi++)
                #pragma unroll
                for (int nb = 0; nb < 4; nb++) {
                    mma16816(acc[mi][nb * 2],     abuf[cur][mi], bbuf[cur][nb][0], bbuf[cur][nb][2]);
                    mma16816(acc[mi][nb * 2 + 1], abuf[cur][mi], bbuf[cur][nb][1], bbuf[cur][nb][3]);
                }
        }
    }

    if (tid < 128) {
        sqi_s[tid] = g_sq[by * 128 + tid];
        sqj_s[tid] = g_sq[bx * 128 + tid];
    }
    __syncthreads();

    float* tbuf = (float*)(smem + (stage_base - sb));   // 128 x 129 fp32

    #pragma unroll
    for (int mi = 0; mi < 2; mi++)
        #pragma unroll
        for (int ni = 0; ni < 8; ni++)
            #pragma unroll
            for (int cc = 0; cc < 4; cc++) {
                int row = wr * 32 + mi * 16 + (lane >> 2) + ((cc >> 1) * 8);
                int col = wc * 64 + ni * 8 + (lane & 3) * 2 + (cc & 1);
                float d2 = sqi_s[row] + sqj_s[col] - 2.f * acc[mi][ni][cc];
                tbuf[row * 129 + col] = sqrtf(fmaxf(d2, 0.f));
            }
    __syncthreads();

    int col = tid & 127, r0 = tid >> 7;
    for (int rr = r0; rr < 128; rr += 2)
        g_Dh[(size_t)(by * 128 + rr) * N + bx * 128 + col] = __float2half(tbuf[rr * 129 + col]);
    if (bx != by)
        for (int rr = r0; rr < 128; rr += 2)
            g_Dh[(size_t)(bx * 128 + rr) * N + by * 128 + col] = __float2half(tbuf[col * 129 + rr]);
}

// ---------------- 3) persistent Boruvka MST (pairs only) ----------------
__global__ void __launch_bounds__(MTHR, 1) mst_kernel() {
    __shared__ unsigned short sroot16[N];   // 4KB
    const int bid  = blockIdx.x;
    const int tid  = threadIdx.x;
    const int gtid = bid * MTHR + tid;
    const int lane = tid & 31;
    const int wrp  = tid >> 5;
    const int WPC  = MTHR / 32;
    const int NW   = MBLKS * WPC;

    unsigned ls = g_barSense;

    if (gtid == 0) g_cnt = 0;
    for (int i = gtid; i < N; i += MBLKS * MTHR) { g_parent[i] = i; g_root[i] = i; }
    for (int i = gtid; i < ROUNDS * N; i += MBLKS * MTHR) ((ull*)g_minER)[i] = ~0ull;
    gbar(&ls);

    for (int r = 0; r < ROUNDS; r++) {
        if (r > 0) {
            // roots into smem (u16) + global snapshot by CTA 0
            for (int j = tid; j < N; j += MTHR) {
                int p = g_parent[j];
                int pp = g_parent[p];
                while (pp != p) { p = pp; pp = g_parent[p]; }
                sroot16[j] = (unsigned short)p;
                if (bid == 0) g_root[j] = p;
            }
            __syncthreads();
        }

        // warp-per-vertex scan over fp16 rows; 32-bit packed keys (h16<<16 | j)
        for (int v = bid * WPC + wrp; v < N; v += NW) {
            int cv = (r == 0) ? v : (int)sroot16[v];
            const uint4* __restrict__ row4 = (const uint4*)(g_Dh + (size_t)v * N);
            unsigned best = 0xFFFFFFFFu;
            if (r == 0) {
                #pragma unroll 2
                for (int q = lane; q < N / 8; q += 32) {
                    uint4 dv = row4[q];
                    int j = q * 8;
                    unsigned h;
                    h = dv.x & 0xffffu;  if (j     != v) best = min(best, (h << 16) | (unsigned)(j));
                    h = dv.x >> 16;      if (j + 1 != v) best = min(best, (h << 16) | (unsigned)(j + 1));
                    h = dv.y & 0xffffu;  if (j + 2 != v) best = min(best, (h << 16) | (unsigned)(j + 2));
                    h = dv.y >> 16;      if (j + 3 != v) best = min(best, (h << 16) | (unsigned)(j + 3));
                    h = dv.z & 0xffffu;  if (j + 4 != v) best = min(best, (h << 16) | (unsigned)(j + 4));
                    h = dv.z >> 16;      if (j + 5 != v) best = min(best, (h << 16) | (unsigned)(j + 5));
                    h = dv.w & 0xffffu;  if (j + 6 != v) best = min(best, (h << 16) | (unsigned)(j + 6));
                    h = dv.w >> 16;      if (j + 7 != v) best = min(best, (h << 16) | (unsigned)(j + 7));
                }
            } else {
                const uint4* sr4 = (const uint4*)sroot16;
                #pragma unroll 2
                for (int q = lane; q < N / 8; q += 32) {
                    uint4 dv = row4[q];
                    uint4 rv = sr4[q];
                    int j = q * 8;
                    unsigned h;
                    h = dv.x & 0xffffu;  if ((int)(rv.x & 0xffffu) != cv) best = min(best, (h << 16) | (unsigned)(j));
                    h = dv.x >> 16;      if ((int)(rv.x >> 16)     != cv) best = min(best, (h << 16) | (unsigned)(j + 1));
                    h = dv.y & 0xffffu;  if ((int)(rv.y & 0xffffu) != cv) best = min(best, (h << 16) | (unsigned)(j + 2));
                    h = dv.y >> 16;      if ((int)(rv.y >> 16)     != cv) best = min(best, (h << 16) | (unsigned)(j + 3));
                    h = dv.z & 0xffffu;  if ((int)(rv.z & 0xffffu) != cv) best = min(best, (h << 16) | (unsigned)(j + 4));
                    h = dv.z >> 16;      if ((int)(rv.z >> 16)     != cv) best = min(best, (h << 16) | (unsigned)(j + 5));
                    h = dv.w & 0xffffu;  if ((int)(rv.w & 0xffffu) != cv) best = min(best, (h << 16) | (unsigned)(j + 6));
                    h = dv.w >> 16;      if ((int)(rv.w >> 16)     != cv) best = min(best, (h << 16) | (unsigned)(j + 7));
                }
            }
            #pragma unroll
            for (int o = 16; o > 0; o >>= 1)
                best = min(best, __shfl_down_sync(0xffffffffu, best, o));
            if (lane == 0 && best != 0xFFFFFFFFu) {
                __half hh = __ushort_as_half((unsigned short)(best >> 16));
                float wf = __half2float(hh);
                ull key = (((ull)__float_as_uint(wf)) << 32) |
                          (unsigned)((v << 11) | (best & 0x7FFu));
                atomicMin(&g_minER[r][cv], key);
            }
        }
        gbar(&ls);

        // merge: one thread per component root
        if (gtid < N) {
            int c = gtid;
            if (g_parent[c] == c) {
                ull key = g_minER[r][c];
                if (key != ~0ull) {
                    unsigned p = (unsigned)key;
                    int a = (p >> 11) & 2047, b = p & 2047;
                    int ra = g_root[a], rb = g_root[b];
                    int rd = (ra == c) ? rb : ra;
                    bool skip = false;
                    ull key2 = g_minER[r][rd];
                    if (key2 != ~0ull) {
                        unsigned p2 = (unsigned)key2;
                        int a2 = (p2 >> 11) & 2047, b2 = p2 & 2047;
                        int ra2 = g_root[a2], rb2 = g_root[b2];
                        int tgt = (ra2 == rd) ? rb2 : ra2;
                        if (tgt == c && c > rd) skip = true;
                    }
                    if (!skip) {
                        g_parent[c] = rd;
                        g_edgeP[atomicAdd(&g_cnt, 1)] = p & 0x3FFFFFu;
                    }
                }
            }
        }
        gbar(&ls);

        int cnt = *(volatile int*)&g_cnt;
        if (cnt == N - 1) break;
    }
}

// ---------------- 4) exact recompute of selected distances ----------------
__global__ void recompute_kernel(float* __restrict__ w_out) {
    int wrpg = (blockIdx.x * blockDim.x + threadIdx.x) >> 5;
    int lane = threadIdx.x & 31;
    if (wrpg >= N - 1) return;
    unsigned p = g_edgeP[wrpg];
    int a = (p >> 11) & 2047, b = p & 2047;
    const float4* ra = (const float4*)(g_Xb + (size_t)a * K);  // 8 bf16 per float4
    const float4* rb = (const float4*)(g_Xb + (size_t)b * K);
    float s = 0.f;
    #pragma unroll 4
    for (int q = lane; q < K / 8; q += 32) {
        float4 va = ra[q], vb = rb[q];
        const __nv_bfloat162* pa = (const __nv_bfloat162*)&va;
        const __nv_bfloat162* pb = (const __nv_bfloat162*)&vb;
        #pragma unroll
        for (int t = 0; t < 4; t++) {
            float2 fa = __bfloat1622float2(pa[t]);
            float2 fb = __bfloat1622float2(pb[t]);
            s = fmaf(fa.x, fb.x, s);
            s = fmaf(fa.y, fb.y, s);
        }
    }
    #pragma unroll
    for (int o = 16; o > 0; o >>= 1) s += __shfl_down_sync(0xffffffffu, s, o);
    if (lane == 0) {
        float d2 = g_sq[a] + g_sq[b] - 2.f * s;
        w_out[wrpg] = sqrtf(fmaxf(d2, 0.f));
    }
}
__device__ float g_wExact[N];

// ---------------- 5) bitonic sort, write output ----------------
__global__ void sort_out_kernel(float* __restrict__ out) {
    __shared__ float s[N];
    int tid = threadIdx.x;
    for (int i = tid; i < N; i += 1024)
        s[i] = (i < N - 1) ? g_wExact[i] : 3.4028235e38f;
    __syncthreads();
    for (int k = 2; k <= N; k <<= 1) {
        for (int j = k >> 1; j > 0; j >>= 1) {
            for (int i = tid; i < N; i += 1024) {
                int l = i ^ j;
                if (l > i) {
                    bool up = ((i & k) == 0);
                    float a = s[i], b = s[l];
                    if ((a > b) == up) { s[i] = b; s[l] = a; }
                }
            }
            __syncthreads();
        }
    }
    for (int i = tid; i < N - 1; i += 1024) out[i] = s[i];
}

// ---------------- launch ----------------
extern "C" void kernel_launch(void* const* d_in, const int* in_sizes, int n_in,
                              void* d_out, int out_size) {
    const float* x = (const float*)d_in[0];
    float* out = (float*)d_out;

    prep_kernel<<<N, 256>>>(x);

    static const int SMEM_SZ = STAGES * STAGE_BYTES + 1024;
    cudaFuncSetAttribute(gemm_dist_kernel,
                         cudaFuncAttributeMaxDynamicSharedMemorySize, SMEM_SZ);
    gemm_dist_kernel<<<dim3(16, 16), 256, SMEM_SZ>>>();

    mst_kernel<<<MBLKS, MTHR>>>();

    float* wexact;
    cudaGetSymbolAddress((void**)&wexact, g_wExact);
    recompute_kernel<<<256, 256>>>(wexact);
    sort_out_kernel<<<1, 1024>>>(out);
}

// round 8
// speedup vs baseline: 1.5016x; 1.0600x over previous
#include <cuda_runtime.h>
#include <cuda_bf16.h>
#include <cuda_fp16.h>
#include <cstdint>
#include <math.h>

#define N 2048
#define K 4096
#define ROUNDS 11
#define STAGES 3
#define CHUNKS 32              // K-chunks of 128 bf16 (two 64-wide sub-chunks)
#define STAGE_BYTES 65536      // [A0 16K | B0 16K | A1 16K | B1 16K]
#define MBLKS 32
#define MTHR 512

typedef unsigned long long ull;

// ---------------- device scratch ----------------
__device__ __half        g_Dh[(size_t)N * N];    // 8 MB fp16 distance matrix
__device__ __nv_bfloat16 g_Xb[(size_t)N * K];    // 16 MB
__device__ float         g_sq[N];
__device__ int           g_parent[N];
__device__ int           g_root[N];
__device__ ull           g_minER[ROUNDS][N];
__device__ float         g_edgeW[N];
__device__ int           g_cnt;
__device__ unsigned      g_barCount;
__device__ volatile unsigned g_barSense;

// ---------------- helpers ----------------
__device__ __forceinline__ uint32_t s2u(const void* p) {
    return (uint32_t)__cvta_generic_to_shared(p);
}
__device__ __forceinline__ void cp16(uint32_t dst, const void* src) {
    asm volatile("cp.async.cg.shared.global [%0], [%1], 16;" :: "r"(dst), "l"(src) : "memory");
}
__device__ __forceinline__ uint32_t swz(uint32_t off) {
    return off ^ ((off >> 3) & 0x70);
}
__device__ __forceinline__ void ldmx4(uint32_t* r, uint32_t addr) {
    asm volatile("ldmatrix.sync.aligned.m8n8.x4.shared.b16 {%0,%1,%2,%3}, [%4];"
                 : "=r"(r[0]), "=r"(r[1]), "=r"(r[2]), "=r"(r[3]) : "r"(addr));
}
__device__ __forceinline__ void mma16816(float* d, const uint32_t* a, uint32_t b0, uint32_t b1) {
    asm volatile(
        "mma.sync.aligned.m16n8k16.row.col.f32.bf16.bf16.f32 "
        "{%0,%1,%2,%3}, {%4,%5,%6,%7}, {%8,%9}, {%0,%1,%2,%3};"
        : "+f"(d[0]), "+f"(d[1]), "+f"(d[2]), "+f"(d[3])
        : "r"(a[0]), "r"(a[1]), "r"(a[2]), "r"(a[3]), "r"(b0), "r"(b1));
}

__device__ __forceinline__ void gbar(unsigned* ls) {
    __threadfence();
    __syncthreads();
    if (threadIdx.x == 0) {
        unsigned s = *ls ^ 1u;
        *ls = s;
        unsigned old = atomicAdd(&g_barCount, 1u);
        if (old == MBLKS - 1) {
            g_barCount = 0;
            __threadfence();
            g_barSense = s;
        } else {
            while (g_barSense != s) __nanosleep(32);
        }
        __threadfence();
    }
    __syncthreads();
}

// ---------------- 1) fused convert + row squared norms ----------------
__global__ void prep_kernel(const float* __restrict__ x) {
    int row = blockIdx.x;
    int tid = threadIdx.x;
    const float4* xr = (const float4*)(x + (size_t)row * K);
    __nv_bfloat16* xb = g_Xb + (size_t)row * K;
    float s = 0.f;
    #pragma unroll 4
    for (int i = tid; i < K / 4; i += 256) {
        float4 v = xr[i];
        s += v.x * v.x + v.y * v.y + v.z * v.z + v.w * v.w;
        *(__nv_bfloat162*)(xb + i * 4)     = __floats2bfloat162_rn(v.x, v.y);
        *(__nv_bfloat162*)(xb + i * 4 + 2) = __floats2bfloat162_rn(v.z, v.w);
    }
    for (int o = 16; o > 0; o >>= 1) s += __shfl_down_sync(0xffffffffu, s, o);
    __shared__ float ws[8];
    if ((tid & 31) == 0) ws[tid >> 5] = s;
    __syncthreads();
    if (tid == 0) {
        float t = 0.f;
        #pragma unroll
        for (int w = 0; w < 8; w++) t += ws[w];
        g_sq[row] = t;
    }
}

// ---------------- 2) bf16 HMMA GEMM + fp16 distance epilogue ----------------
// BM=BN=128, chunk=128 (two 64-wide sub-chunks), 3-stage cp.async pipeline.
__global__ void __launch_bounds__(256, 1) gemm_dist_kernel() {
    extern __shared__ char smem[];
    const int bx = blockIdx.x, by = blockIdx.y;
    if (bx > by) return;

    const int tid  = threadIdx.x;
    const int wid  = tid >> 5;
    const int lane = tid & 31;
    const int wr   = wid >> 1;
    const int wc   = wid & 1;

    uint32_t sb = s2u(smem);
    uint32_t stage_base = (sb + 1023) & ~1023u;

    __shared__ float sqi_s[128], sqj_s[128];

    const __nv_bfloat16* gA = g_Xb + (size_t)(by * 128) * K;
    const __nv_bfloat16* gB = g_Xb + (size_t)(bx * 128) * K;

    // stage s holds chunk pair: sub-chunk h at stage+h*32768 ([A 16K | B 16K])
    auto load_stage = [&](int s, int chunk) {
        #pragma unroll
        for (int h = 0; h < 2; h++) {
            uint32_t bA = stage_base + s * STAGE_BYTES + h * 32768;
            uint32_t bB = bA + 16384;
            size_t kb = ((size_t)chunk * 2 + h) * 128;   // byte offset in row (64 bf16)
            #pragma unroll
            for (int it = 0; it < 4; it++) {
                int q = tid + it * 256;
                int r = q >> 3, c = q & 7;
                uint32_t sw = swz((uint32_t)(r * 128 + c * 16));
                cp16(bA + sw, (const char*)(gA + (size_t)r * K) + kb + c * 16);
                cp16(bB + sw, (const char*)(gB + (size_t)r * K) + kb + c * 16);
            }
        }
    };

    float acc[2][8][4];
    #pragma unroll
    for (int i = 0; i < 2; i++)
        #pragma unroll
        for (int j = 0; j < 8; j++)
            #pragma unroll
            for (int c = 0; c < 4; c++) acc[i][j][c] = 0.f;

    load_stage(0, 0);
    asm volatile("cp.async.commit_group;" ::: "memory");
    load_stage(1, 1);
    asm volatile("cp.async.commit_group;" ::: "memory");

    const int rowA0 = wr * 32 + (lane & 15);
    const int rowB0 = wc * 64 + (lane & 15);
    const int hb    = (lane >> 4) * 16;

    for (int c = 0; c < CHUNKS; c++) {
        int s = c % STAGES;
        asm volatile("cp.async.wait_group 1;" ::: "memory");
        __syncthreads();

        if (c + 2 < CHUNKS) load_stage((c + 2) % STAGES, c + 2);
        asm volatile("cp.async.commit_group;" ::: "memory");

        uint32_t base = stage_base + s * STAGE_BYTES;

        // 8-step kk pipeline across the two sub-chunks, register double-buffered
        uint32_t abuf[2][2][4], bbuf[2][4][4];
        auto addrA = [&](int kk, int mi) {
            return base + (kk >> 2) * 32768 +
                   swz((uint32_t)((rowA0 + mi * 16) * 128 + (kk & 3) * 32 + hb));
        };
        auto addrB = [&](int kk, int nb) {
            return base + (kk >> 2) * 32768 + 16384 +
                   swz((uint32_t)((rowB0 + nb * 16) * 128 + (kk & 3) * 32 + hb));
        };
        #pragma unroll
        for (int mi = 0; mi < 2; mi++) ldmx4(abuf[0][mi], addrA(0, mi));
        #pragma unroll
        for (int nb = 0; nb < 4; nb++) ldmx4(bbuf[0][nb], addrB(0, nb));

        #pragma unroll
        for (int kk = 0; kk < 8; kk++) {
            int cur = kk & 1, nxt = cur ^ 1;
            if (kk < 7) {
                #pragma unroll
                for (int mi = 0; mi < 2; mi++) ldmx4(abuf[nxt][mi], addrA(kk + 1, mi));
                #pragma unroll
                for (int nb = 0; nb < 4; nb++) ldmx4(bbuf[nxt][nb], addrB(kk + 1, nb));
            }
            #pragma unroll
            for (int mi = 0; mi < 2; mi++)
                #pragma unroll
                for (int nb = 0; nb < 4; nb++) {
                    mma16816(acc[mi][nb * 2],     abuf[cur][mi], bbuf[cur][nb][0], bbuf[cur][nb][2]);
                    mma16816(acc[mi][nb * 2 + 1], abuf[cur][mi], bbuf[cur][nb][1], bbuf[cur][nb][3]);
                }
        }
    }

    if (tid < 128) {
        sqi_s[tid] = g_sq[by * 128 + tid];
        sqj_s[tid] = g_sq[bx * 128 + tid];
    }
    __syncthreads();

    float* tbuf = (float*)(smem + (stage_base - sb));   // 128 x 129 fp32 (66KB)

    #pragma unroll
    for (int mi = 0; mi < 2; mi++)
        #pragma unroll
        for (int ni = 0; ni < 8; ni++)
            #pragma unroll
            for (int cc = 0; cc < 4; cc++) {
                int row = wr * 32 + mi * 16 + (lane >> 2) + ((cc >> 1) * 8);
                int col = wc * 64 + ni * 8 + (lane & 3) * 2 + (cc & 1);
                float d2 = sqi_s[row] + sqj_s[col] - 2.f * acc[mi][ni][cc];
                tbuf[row * 129 + col] = sqrtf(fmaxf(d2, 0.f));
            }
    __syncthreads();

    int col = tid & 127, r0 = tid >> 7;
    for (int rr = r0; rr < 128; rr += 2)
        g_Dh[(size_t)(by * 128 + rr) * N + bx * 128 + col] = __float2half(tbuf[rr * 129 + col]);
    if (bx != by)
        for (int rr = r0; rr < 128; rr += 2)
            g_Dh[(size_t)(bx * 128 + rr) * N + by * 128 + col] = __float2half(tbuf[col * 129 + rr]);
}

// ---------------- 3) persistent Boruvka MST ----------------
__global__ void __launch_bounds__(MTHR, 1) mst_kernel() {
    __shared__ unsigned short sroot16[N];   // 4KB
    const int bid  = blockIdx.x;
    const int tid  = threadIdx.x;
    const int gtid = bid * MTHR + tid;
    const int lane = tid & 31;
    const int wrp  = tid >> 5;
    const int WPC  = MTHR / 32;
    const int NW   = MBLKS * WPC;

    unsigned ls = g_barSense;

    if (gtid == 0) g_cnt = 0;
    for (int i = gtid; i < N; i += MBLKS * MTHR) { g_parent[i] = i; g_root[i] = i; }
    for (int i = gtid; i < ROUNDS * N; i += MBLKS * MTHR) ((ull*)g_minER)[i] = ~0ull;
    gbar(&ls);

    for (int r = 0; r < ROUNDS; r++) {
        if (r > 0) {
            for (int j = tid; j < N; j += MTHR) {
                int p = g_parent[j];
                int pp = g_parent[p];
                while (pp != p) { p = pp; pp = g_parent[p]; }
                sroot16[j] = (unsigned short)p;
                if (bid == 0) g_root[j] = p;
            }
            __syncthreads();
        }

        for (int v = bid * WPC + wrp; v < N; v += NW) {
            int cv = (r == 0) ? v : (int)sroot16[v];
            const uint4* __restrict__ row4 = (const uint4*)(g_Dh + (size_t)v * N);
            unsigned best = 0xFFFFFFFFu;
            if (r == 0) {
                #pragma unroll 2
                for (int q = lane; q < N / 8; q += 32) {
                    uint4 dv = row4[q];
                    int j = q * 8;
                    unsigned h;
                    h = dv.x & 0xffffu;  if (j     != v) best = min(best, (h << 16) | (unsigned)(j));
                    h = dv.x >> 16;      if (j + 1 != v) best = min(best, (h << 16) | (unsigned)(j + 1));
                    h = dv.y & 0xffffu;  if (j + 2 != v) best = min(best, (h << 16) | (unsigned)(j + 2));
                    h = dv.y >> 16;      if (j + 3 != v) best = min(best, (h << 16) | (unsigned)(j + 3));
                    h = dv.z & 0xffffu;  if (j + 4 != v) best = min(best, (h << 16) | (unsigned)(j + 4));
                    h = dv.z >> 16;      if (j + 5 != v) best = min(best, (h << 16) | (unsigned)(j + 5));
                    h = dv.w & 0xffffu;  if (j + 6 != v) best = min(best, (h << 16) | (unsigned)(j + 6));
                    h = dv.w >> 16;      if (j + 7 != v) best = min(best, (h << 16) | (unsigned)(j + 7));
                }
            } else {
                const uint4* sr4 = (const uint4*)sroot16;
                #pragma unroll 2
                for (int q = lane; q < N / 8; q += 32) {
                    uint4 dv = row4[q];
                    uint4 rv = sr4[q];
                    int j = q * 8;
                    unsigned h;
                    h = dv.x & 0xffffu;  if ((int)(rv.x & 0xffffu) != cv) best = min(best, (h << 16) | (unsigned)(j));
                    h = dv.x >> 16;      if ((int)(rv.x >> 16)     != cv) best = min(best, (h << 16) | (unsigned)(j + 1));
                    h = dv.y & 0xffffu;  if ((int)(rv.y & 0xffffu) != cv) best = min(best, (h << 16) | (unsigned)(j + 2));
                    h = dv.y >> 16;      if ((int)(rv.y >> 16)     != cv) best = min(best, (h << 16) | (unsigned)(j + 3));
                    h = dv.z & 0xffffu;  if ((int)(rv.z & 0xffffu) != cv) best = min(best, (h << 16) | (unsigned)(j + 4));
                    h = dv.z >> 16;      if ((int)(rv.z >> 16)     != cv) best = min(best, (h << 16) | (unsigned)(j + 5));
                    h = dv.w & 0xffffu;  if ((int)(rv.w & 0xffffu) != cv) best = min(best, (h << 16) | (unsigned)(j + 6));
                    h = dv.w >> 16;      if ((int)(rv.w >> 16)     != cv) best = min(best, (h << 16) | (unsigned)(j + 7));
                }
            }
            #pragma unroll
            for (int o = 16; o > 0; o >>= 1)
                best = min(best, __shfl_down_sync(0xffffffffu, best, o));
            if (lane == 0 && best != 0xFFFFFFFFu) {
                __half hh = __ushort_as_half((unsigned short)(best >> 16));
                float wf = __half2float(hh);
                ull key = (((ull)__float_as_uint(wf)) << 32) |
                          (unsigned)((v << 11) | (best & 0x7FFu));
                atomicMin(&g_minER[r][cv], key);
            }
        }
        gbar(&ls);

        if (gtid < N) {
            int c = gtid;
            if (g_parent[c] == c) {
                ull key = g_minER[r][c];
                if (key != ~0ull) {
                    unsigned p = (unsigned)key;
                    int a = (p >> 11) & 2047, b = p & 2047;
                    int ra = g_root[a], rb = g_root[b];
                    int rd = (ra == c) ? rb : ra;
                    bool skip = false;
                    ull key2 = g_minER[r][rd];
                    if (key2 != ~0ull) {
                        unsigned p2 = (unsigned)key2;
                        int a2 = (p2 >> 11) & 2047, b2 = p2 & 2047;
                        int ra2 = g_root[a2], rb2 = g_root[b2];
                        int tgt = (ra2 == rd) ? rb2 : ra2;
                        if (tgt == c && c > rd) skip = true;
                    }
                    if (!skip) {
                        g_parent[c] = rd;
                        g_edgeW[atomicAdd(&g_cnt, 1)] = __uint_as_float((unsigned)(key >> 32));
                    }
                }
            }
        }
        gbar(&ls);

        int cnt = *(volatile int*)&g_cnt;
        if (cnt == N - 1) break;
    }
}

// ---------------- 4) bitonic sort, write output ----------------
__global__ void sort_out_kernel(float* __restrict__ out) {
    __shared__ float s[N];
    int tid = threadIdx.x;
    for (int i = tid; i < N; i += 1024)
        s[i] = (i < N - 1) ? g_edgeW[i] : 3.4028235e38f;
    __syncthreads();
    for (int k = 2; k <= N; k <<= 1) {
        for (int j = k >> 1; j > 0; j >>= 1) {
            for (int i = tid; i < N; i += 1024) {
                int l = i ^ j;
                if (l > i) {
                    bool up = ((i & k) == 0);
                    float a = s[i], b = s[l];
                    if ((a > b) == up) { s[i] = b; s[l] = a; }
                }
            }
            __syncthreads();
        }
    }
    for (int i = tid; i < N - 1; i += 1024) out[i] = s[i];
}

// ---------------- launch ----------------
extern "C" void kernel_launch(void* const* d_in, const int* in_sizes, int n_in,
                              void* d_out, int out_size) {
    const float* x = (const float*)d_in[0];
    float* out = (float*)d_out;

    prep_kernel<<<N, 256>>>(x);

    static const int SMEM_SZ = STAGES * STAGE_BYTES + 1024;   // ~197KB
    cudaFuncSetAttribute(gemm_dist_kernel,
                         cudaFuncAttributeMaxDynamicSharedMemorySize, SMEM_SZ);
    gemm_dist_kernel<<<dim3(16, 16), 256, SMEM_SZ>>>();

    mst_kernel<<<MBLKS, MTHR>>>();
    sort_out_kernel<<<1, 1024>>>(out);
}